// round 16
// baseline (speedup 1.0000x reference)
#include <cuda_runtime.h>
#include <math_constants.h>
#include <math.h>
#include <stdint.h>

#define D_MODEL   768
#define NUM_HEADS 12
#define HEAD_DIM  64
#define BATCH     4
#define SEQ       1024
#define NTOK      (BATCH*SEQ)
#define LOG2E     1.4426950408889634f

// ---------------- scratch ----------------------------------------------------
__device__ float g_Q[NTOK * D_MODEL];     // [b,h,s,d]
__device__ float g_K[NTOK * D_MODEL];     // [b,h,s,d]
__device__ float g_V[NTOK * D_MODEL];     // [b,h,s,d]
__device__ float g_att[NTOK * D_MODEL];   // [b,s, h*64+d] flat [4096,768]
__device__ float g_cx[NTOK];
__device__ float g_cy[NTOK];

// ---------------- box centers ----------------------------------------------
__global__ void centers_kernel(const float* __restrict__ boxes) {
    int i = blockIdx.x * blockDim.x + threadIdx.x;
    if (i < NTOK) {
        float4 bx = *(const float4*)(boxes + (size_t)i * 4);
        g_cx[i] = (bx.x + bx.z) * 0.5f;
        g_cy[i] = (bx.y + bx.w) * 0.5f;
    }
}

// ---------------- tf32 / fast-math helpers ----------------------------------
__device__ __forceinline__ uint32_t to_tf32(float x) {
    uint32_t r;
    asm("cvt.rna.tf32.f32 %0, %1;" : "=r"(r) : "f"(x));
    return r;
}

__device__ __forceinline__ void mma_tf32(float* c, uint32_t a0, uint32_t a1,
                                         uint32_t a2, uint32_t a3,
                                         uint32_t b0, uint32_t b1) {
    asm volatile(
        "mma.sync.aligned.m16n8k8.row.col.f32.tf32.tf32.f32 "
        "{%0,%1,%2,%3}, {%4,%5,%6,%7}, {%8,%9}, {%0,%1,%2,%3};\n"
        : "+f"(c[0]), "+f"(c[1]), "+f"(c[2]), "+f"(c[3])
        : "r"(a0), "r"(a1), "r"(a2), "r"(a3), "r"(b0), "r"(b1));
}

__device__ __forceinline__ float rsqrt_approx(float x) {
    float r;
    asm("rsqrt.approx.f32 %0, %1;" : "=f"(r) : "f"(x));
    return r;
}
__device__ __forceinline__ float fast_dist(float dx, float dy) {
    float s = dx * dx + dy * dy;
    return s * rsqrt_approx(fmaxf(s, 1e-30f));
}
__device__ __forceinline__ float ex2_approx(float x) {
    float r;
    asm("ex2.approx.f32 %0, %1;" : "=f"(r) : "f"(x));
    return r;
}

// ---------------- TF32 tensor-core GEMM body: BK=32 -------------------------
// BM=BN=128, BK=32. Paired-k smem, row stride 40 words: fragment LDS.64 banks
// (40*m + ks*8 + 2q)/2 mod 16 = 4*(lane>>2)+(lane&3) mod 16 -> exact 16-cover
// per phase, conflict-free (stride 36 was NOT: 2-way). Split staging: threads
// 0..127 stage A rows, 128..255 stage W rows. Double buffered, ONE barrier
// per 32-k iteration (24 total vs 48 at BK=16).
#define GSTRIDE 40
#define GBUF_WORDS (128 * GSTRIDE)                  // per matrix per buffer
#define GEMM_SMEM_BYTES (2 * 2 * GBUF_WORDS * 4)    // 81920 B

template<int LAYOUT>
__device__ __forceinline__ void gemm_body(
    const float* __restrict__ A, const float* __restrict__ W,
    const float* __restrict__ bias, float* __restrict__ out)
{
    extern __shared__ uint32_t gsm[];
    uint32_t* As = gsm;                       // [2][128][40]
    uint32_t* Ws = gsm + 2 * GBUF_WORDS;      // [2][128][40]

    const int t    = threadIdx.x;
    const int lane = t & 31;
    const int warp = t >> 5;
    const int wm   = warp & 1;
    const int wn   = warp >> 1;
    const int row0 = blockIdx.y * 128;
    const int col0 = blockIdx.x * 128;

    // split staging: lower half stages A, upper half stages W
    const bool doA  = (t < 128);
    const int  srow = t & 127;
    const float* src = doA ? (A + (size_t)(row0 + srow) * D_MODEL)
                           : (W + (size_t)(col0 + srow) * D_MODEL);
    uint32_t* dstbase = (doA ? As : Ws) + srow * GSTRIDE;

    float acc[4][4][4];
#pragma unroll
    for (int mt = 0; mt < 4; mt++)
#pragma unroll
        for (int nt = 0; nt < 4; nt++)
#pragma unroll
            for (int r = 0; r < 4; r++) acc[mt][nt][r] = 0.f;

    float4 f[8];
#pragma unroll
    for (int u = 0; u < 8; u++) f[u] = *(const float4*)(src + 4 * u);
    // stage tile 0 -> buffer 0
    {
        uint32_t* d = dstbase;
#pragma unroll
        for (int g = 0; g < 4; g++) {
            float4 a = f[2 * g], b = f[2 * g + 1];
            *(uint4*)(d + g * 8 + 0) = make_uint4(to_tf32(a.x), to_tf32(b.x),
                                                  to_tf32(a.y), to_tf32(b.y));
            *(uint4*)(d + g * 8 + 4) = make_uint4(to_tf32(a.z), to_tf32(b.z),
                                                  to_tf32(a.w), to_tf32(b.w));
        }
    }
    __syncthreads();

    const int NIT = D_MODEL / 32;  // 24
    for (int it = 0; it < NIT; it++) {
        const int cur  = it & 1;
        const bool more = (it + 1) < NIT;
        if (more) {
            const float* s = src + (it + 1) * 32;
#pragma unroll
            for (int u = 0; u < 8; u++) f[u] = *(const float4*)(s + 4 * u);
        }

        const uint32_t* Ab = &As[cur * GBUF_WORDS];
        const uint32_t* Wb = &Ws[cur * GBUF_WORDS];
#pragma unroll
        for (int ks = 0; ks < 4; ks++) {
            const int base = ks * 8 + 2 * (lane & 3);
            uint2 bf[4];
#pragma unroll
            for (int nt = 0; nt < 4; nt++) {
                int n = wn * 32 + nt * 8 + (lane >> 2);
                bf[nt] = *(const uint2*)&Wb[n * GSTRIDE + base];
            }
#pragma unroll
            for (int mt = 0; mt < 4; mt++) {
                int mr = wm * 64 + mt * 16 + (lane >> 2);
                uint2 lo = *(const uint2*)&Ab[mr * GSTRIDE + base];
                uint2 hi = *(const uint2*)&Ab[(mr + 8) * GSTRIDE + base];
#pragma unroll
                for (int nt = 0; nt < 4; nt++)
                    mma_tf32(acc[mt][nt], lo.x, hi.x, lo.y, hi.y, bf[nt].x, bf[nt].y);
            }
        }

        if (more) {
            uint32_t* d = dstbase + (cur ^ 1) * GBUF_WORDS;
#pragma unroll
            for (int g = 0; g < 4; g++) {
                float4 a = f[2 * g], b = f[2 * g + 1];
                *(uint4*)(d + g * 8 + 0) = make_uint4(to_tf32(a.x), to_tf32(b.x),
                                                      to_tf32(a.y), to_tf32(b.y));
                *(uint4*)(d + g * 8 + 4) = make_uint4(to_tf32(a.z), to_tf32(b.z),
                                                      to_tf32(a.w), to_tf32(b.w));
            }
        }
        __syncthreads();
    }

#pragma unroll
    for (int mt = 0; mt < 4; mt++) {
#pragma unroll
        for (int nt = 0; nt < 4; nt++) {
            int r = row0 + wm * 64 + mt * 16 + (lane >> 2);
            int c = col0 + wn * 32 + nt * 8 + (lane & 3) * 2;
            float b0 = bias[c], b1 = bias[c + 1];
#pragma unroll
            for (int half = 0; half < 2; half++) {
                int rr = r + half * 8;
                float v0 = acc[mt][nt][half * 2 + 0] + b0;
                float v1 = acc[mt][nt][half * 2 + 1] + b1;
                size_t base;
                if (LAYOUT == 1) {
                    int b = rr >> 10, s = rr & 1023;
                    int h = c >> 6, d0 = c & 63;
                    base = (((size_t)(b * NUM_HEADS + h)) * SEQ + s) * HEAD_DIM + d0;
                } else {
                    base = (size_t)rr * D_MODEL + c;
                }
                *(float2*)(out + base) = make_float2(v0, v1);
            }
        }
    }
}

__global__ __launch_bounds__(256, 2) void gemm_qkv_kernel(
    const float* __restrict__ x,
    const float* __restrict__ Wq, const float* __restrict__ Wk,
    const float* __restrict__ Wv,
    const float* __restrict__ bq, const float* __restrict__ bk,
    const float* __restrict__ bv,
    float* __restrict__ oq, float* __restrict__ ok, float* __restrict__ ov)
{
    const int z = blockIdx.z;
    const float* W = (z == 0) ? Wq : (z == 1) ? Wk : Wv;
    const float* b = (z == 0) ? bq : (z == 1) ? bk : bv;
    float*       o = (z == 0) ? oq : (z == 1) ? ok : ov;
    gemm_body<1>(x, W, b, o);
}

__global__ __launch_bounds__(256, 2) void gemm_out_kernel(
    const float* __restrict__ A, const float* __restrict__ W,
    const float* __restrict__ bias, float* __restrict__ out)
{
    gemm_body<0>(A, W, bias, out);
}

// ---------------- attention (unchanged from R14) -----------------------------
#define AQ_STR 72
#define KCH_W  (64 * 72)                 // 4608 words
#define OFF_Q   0
#define OFF_KT  (128 * AQ_STR)           // 9216
#define OFF_VT  (OFF_KT + KCH_W)         // 13824
#define OFF_QCX (OFF_VT + KCH_W)         // 18432
#define OFF_QCY (OFF_QCX + 128)          // 18560
#define OFF_KC  (OFF_QCY + 128)          // 18688: [128] = {cx[64], cy[64]}
#define ATTN_SMEM_BYTES ((OFF_KC + 128) * 4)   // 75264 B

__device__ __forceinline__ void stage_paired_q(uint32_t* dst, const float* src,
                                               int t) {
    const int tr = t >> 1;
    const int half = t & 1;
    const float* p = src + (size_t)tr * HEAD_DIM + half * 32;
    float4 f[8];
#pragma unroll
    for (int u = 0; u < 8; u++) f[u] = *(const float4*)(p + 4 * u);
    uint32_t* row = dst + tr * AQ_STR + half * 32;
#pragma unroll
    for (int gg = 0; gg < 4; gg++) {
        float4 lo = f[2 * gg], hi = f[2 * gg + 1];
        *(uint2*)(row + gg * 8 + 0) = make_uint2(to_tf32(lo.x), to_tf32(hi.x));
        *(uint2*)(row + gg * 8 + 2) = make_uint2(to_tf32(lo.y), to_tf32(hi.y));
        *(uint2*)(row + gg * 8 + 4) = make_uint2(to_tf32(lo.z), to_tf32(hi.z));
        *(uint2*)(row + gg * 8 + 6) = make_uint2(to_tf32(lo.w), to_tf32(hi.w));
    }
}

__device__ __forceinline__ void stage_chunk(uint32_t* smu, size_t headbase,
                                            int bS, int ci, int t) {
    const int kr = t >> 2;
    const int cq = (t & 3) * 16;
    const int g0 = cq >> 3;
    const size_t rbase = headbase + (size_t)(ci * 64 + kr) * HEAD_DIM + cq;
    const float* kp = g_K + rbase;
    const float* vp = g_V + rbase;
    float4 fK[4], fV[4];
#pragma unroll
    for (int u = 0; u < 4; u++) {
        fK[u] = *(const float4*)(kp + 4 * u);
        fV[u] = *(const float4*)(vp + 4 * u);
    }
    float cpref = 0.f;
    if (t < 64)       cpref = g_cx[bS + ci * 64 + t];
    else if (t < 128) cpref = g_cy[bS + ci * 64 + (t - 64)];

    const float* fk = (const float*)fK;
    uint32_t* krow = smu + OFF_KT + kr * 72;
#pragma unroll
    for (int gg = 0; gg < 2; gg++) {
        const float* f = fk + gg * 8;
        *(uint4*)(krow + (g0 + gg) * 8 + 0) =
            make_uint4(to_tf32(f[0]), to_tf32(f[4]), to_tf32(f[1]), to_tf32(f[5]));
        *(uint4*)(krow + (g0 + gg) * 8 + 4) =
            make_uint4(to_tf32(f[2]), to_tf32(f[6]), to_tf32(f[3]), to_tf32(f[7]));
    }
    uint32_t* vrow = smu + OFF_VT + kr * 72 + cq;
#pragma unroll
    for (int u = 0; u < 4; u++)
        *(uint4*)(vrow + 4 * u) = make_uint4(to_tf32(fV[u].x), to_tf32(fV[u].y),
                                             to_tf32(fV[u].z), to_tf32(fV[u].w));
    if (t < 128) ((float*)(smu + OFF_KC))[t] = cpref;
}

__global__ __launch_bounds__(256, 3) void attn_kernel(const float* __restrict__ sbias)
{
    extern __shared__ uint32_t smu[];
    uint32_t* Qs = smu + OFF_Q;
    float* qcx = (float*)(smu + OFF_QCX);
    float* qcy = (float*)(smu + OFF_QCY);

    const int t    = threadIdx.x;
    const int lane = t & 31;
    const int warp = t >> 5;
    const int q    = lane & 3;
    const int bh = blockIdx.y;
    const int b  = bh / NUM_HEADS, h = bh % NUM_HEADS;
    const int q0 = blockIdx.x * 128;
    const float sb2 = sbias[h] * LOG2E;
    const float sc2 = 0.125f * LOG2E;
    const size_t headbase = (size_t)bh * SEQ * HEAD_DIM;
    const int bS = b * SEQ;

    const int r0 = warp * 16 + (lane >> 2);
    const int r1 = r0 + 8;

    stage_paired_q(Qs, g_Q + headbase + (size_t)q0 * HEAD_DIM, t);
    if (t < 128) {
        qcx[t] = g_cx[bS + q0 + t];
        qcy[t] = g_cy[bS + q0 + t];
    }
    stage_chunk(smu, headbase, bS, 0, t);
    __syncthreads();

    const float qx0 = qcx[r0], qy0 = qcy[r0];
    const float qx1 = qcx[r1], qy1 = qcy[r1];

    float m0 = -CUDART_INF_F, m1 = -CUDART_INF_F, l0 = 0.f, l1 = 0.f;
    float oacc[8][4];
#pragma unroll
    for (int nt = 0; nt < 8; nt++)
#pragma unroll
        for (int r = 0; r < 4; r++) oacc[nt][r] = 0.f;

    const int sA = (lane & ~3) | (q >> 1);
    const int sB = sA + 2;
    const bool qodd = (q & 1) != 0;

    const uint32_t* Kb = smu + OFF_KT;
    const uint32_t* Vb = smu + OFF_VT;
    const float* kcb = (const float*)(smu + OFF_KC);

    const int NCHUNK = SEQ / 64;  // 16
    for (int ci = 0; ci < NCHUNK; ci++) {
        float sacc[8][4];
#pragma unroll
        for (int nt = 0; nt < 8; nt++)
            sacc[nt][0] = sacc[nt][1] = sacc[nt][2] = sacc[nt][3] = 0.f;
#pragma unroll
        for (int ks = 0; ks < 8; ks++) {
            uint2 qlo = *(const uint2*)&Qs[r0 * AQ_STR + ks * 8 + 2 * q];
            uint2 qhi = *(const uint2*)&Qs[r1 * AQ_STR + ks * 8 + 2 * q];
#pragma unroll
            for (int nt = 0; nt < 8; nt++) {
                int col = nt * 8 + (lane >> 2);
                uint2 bv = *(const uint2*)&Kb[col * 72 + ks * 8 + 2 * q];
                mma_tf32(sacc[nt], qlo.x, qhi.x, qlo.y, qhi.y, bv.x, bv.y);
            }
        }

        float pm0 = -CUDART_INF_F, pm1 = -CUDART_INF_F;
#pragma unroll
        for (int nt = 0; nt < 8; nt++) {
            const int c0 = nt * 8 + 2 * q;
            const float kx0 = kcb[c0], kx1 = kcb[c0 + 1];
            const float ky0 = kcb[64 + c0], ky1 = kcb[64 + c0 + 1];
            sacc[nt][0] = sacc[nt][0] * sc2 - fast_dist(qx0 - kx0, qy0 - ky0) * sb2;
            sacc[nt][1] = sacc[nt][1] * sc2 - fast_dist(qx0 - kx1, qy0 - ky1) * sb2;
            sacc[nt][2] = sacc[nt][2] * sc2 - fast_dist(qx1 - kx0, qy1 - ky0) * sb2;
            sacc[nt][3] = sacc[nt][3] * sc2 - fast_dist(qx1 - kx1, qy1 - ky1) * sb2;
            pm0 = fmaxf(pm0, fmaxf(sacc[nt][0], sacc[nt][1]));
            pm1 = fmaxf(pm1, fmaxf(sacc[nt][2], sacc[nt][3]));
        }
        pm0 = fmaxf(pm0, __shfl_xor_sync(0xffffffffu, pm0, 1));
        pm0 = fmaxf(pm0, __shfl_xor_sync(0xffffffffu, pm0, 2));
        pm1 = fmaxf(pm1, __shfl_xor_sync(0xffffffffu, pm1, 1));
        pm1 = fmaxf(pm1, __shfl_xor_sync(0xffffffffu, pm1, 2));

        const float mn0 = fmaxf(m0, pm0), mn1 = fmaxf(m1, pm1);
        const float sc0 = ex2_approx(m0 - mn0), sc1 = ex2_approx(m1 - mn1);
        m0 = mn0; m1 = mn1;
#pragma unroll
        for (int nt = 0; nt < 8; nt++) {
            oacc[nt][0] *= sc0; oacc[nt][1] *= sc0;
            oacc[nt][2] *= sc1; oacc[nt][3] *= sc1;
        }

        float s0 = 0.f, s1 = 0.f;
#pragma unroll
        for (int nt = 0; nt < 8; nt++) {
            sacc[nt][0] = ex2_approx(sacc[nt][0] - mn0);
            sacc[nt][1] = ex2_approx(sacc[nt][1] - mn0);
            sacc[nt][2] = ex2_approx(sacc[nt][2] - mn1);
            sacc[nt][3] = ex2_approx(sacc[nt][3] - mn1);
            s0 += sacc[nt][0] + sacc[nt][1];
            s1 += sacc[nt][2] + sacc[nt][3];
        }
        s0 += __shfl_xor_sync(0xffffffffu, s0, 1);
        s0 += __shfl_xor_sync(0xffffffffu, s0, 2);
        s1 += __shfl_xor_sync(0xffffffffu, s1, 1);
        s1 += __shfl_xor_sync(0xffffffffu, s1, 2);
        l0 = l0 * sc0 + s0;
        l1 = l1 * sc1 + s1;

#pragma unroll
        for (int ks = 0; ks < 8; ks++) {
            float u0 = __shfl_sync(0xffffffffu, sacc[ks][0], sA);
            float u1 = __shfl_sync(0xffffffffu, sacc[ks][1], sA);
            float v0 = __shfl_sync(0xffffffffu, sacc[ks][0], sB);
            float v1 = __shfl_sync(0xffffffffu, sacc[ks][1], sB);
            float w0 = __shfl_sync(0xffffffffu, sacc[ks][2], sA);
            float w1 = __shfl_sync(0xffffffffu, sacc[ks][3], sA);
            float x0 = __shfl_sync(0xffffffffu, sacc[ks][2], sB);
            float x1 = __shfl_sync(0xffffffffu, sacc[ks][3], sB);
            uint32_t pa0 = to_tf32(qodd ? u1 : u0);
            uint32_t pa2 = to_tf32(qodd ? v1 : v0);
            uint32_t pa1 = to_tf32(qodd ? w1 : w0);
            uint32_t pa3 = to_tf32(qodd ? x1 : x0);

            const int krow = ks * 8 + q;
            const uint32_t* vr0 = &Vb[krow * 72 + (lane >> 2)];
            const uint32_t* vr1 = &Vb[(krow + 4) * 72 + (lane >> 2)];
#pragma unroll
            for (int nt = 0; nt < 8; nt++) {
                uint32_t vb0 = vr0[nt * 8];
                uint32_t vb1 = vr1[nt * 8];
                mma_tf32(oacc[nt], pa0, pa1, pa2, pa3, vb0, vb1);
            }
        }

        if (ci + 1 < NCHUNK) {
            __syncthreads();
            stage_chunk(smu, headbase, bS, ci + 1, t);
            __syncthreads();
        }
    }

    const float inv0 = 1.f / l0, inv1 = 1.f / l1;
#pragma unroll
    for (int nt = 0; nt < 8; nt++) {
        const int d0 = nt * 8 + 2 * q;
        size_t base0 = ((size_t)(bS + q0 + r0)) * D_MODEL + h * HEAD_DIM + d0;
        size_t base1 = ((size_t)(bS + q0 + r1)) * D_MODEL + h * HEAD_DIM + d0;
        *(float2*)(g_att + base0) = make_float2(oacc[nt][0] * inv0, oacc[nt][1] * inv0);
        *(float2*)(g_att + base1) = make_float2(oacc[nt][2] * inv1, oacc[nt][3] * inv1);
    }
}

// ---------------- launch ----------------------------------------------------
extern "C" void kernel_launch(void* const* d_in, const int* in_sizes, int n_in,
                              void* d_out, int out_size)
{
    const float* x     = (const float*)d_in[0];
    const float* boxes = (const float*)d_in[1];
    const float* Wq    = (const float*)d_in[2];
    const float* bq    = (const float*)d_in[3];
    const float* Wk    = (const float*)d_in[4];
    const float* bk    = (const float*)d_in[5];
    const float* Wv    = (const float*)d_in[6];
    const float* bv    = (const float*)d_in[7];
    const float* Wo    = (const float*)d_in[8];
    const float* bo    = (const float*)d_in[9];
    const float* sbias = (const float*)d_in[10];
    float* out = (float*)d_out;

    float *pQ, *pK, *pV, *pAtt;
    cudaGetSymbolAddress((void**)&pQ,   g_Q);
    cudaGetSymbolAddress((void**)&pK,   g_K);
    cudaGetSymbolAddress((void**)&pV,   g_V);
    cudaGetSymbolAddress((void**)&pAtt, g_att);

    cudaFuncSetAttribute(gemm_qkv_kernel,
        cudaFuncAttributeMaxDynamicSharedMemorySize, GEMM_SMEM_BYTES);
    cudaFuncSetAttribute(gemm_out_kernel,
        cudaFuncAttributeMaxDynamicSharedMemorySize, GEMM_SMEM_BYTES);
    cudaFuncSetAttribute(attn_kernel,
        cudaFuncAttributeMaxDynamicSharedMemorySize, ATTN_SMEM_BYTES);

    centers_kernel<<<(NTOK + 255) / 256, 256>>>(boxes);

    dim3 qkvgrid(D_MODEL / 128, NTOK / 128, 3);   // (6, 32, 3)
    gemm_qkv_kernel<<<qkvgrid, 256, GEMM_SMEM_BYTES>>>(
        x, Wq, Wk, Wv, bq, bk, bv, pQ, pK, pV);

    dim3 agrid(SEQ / 128, BATCH * NUM_HEADS);     // (8, 48)
    attn_kernel<<<agrid, 256, ATTN_SMEM_BYTES>>>(sbias);

    dim3 ogrid(D_MODEL / 128, NTOK / 128);        // (6, 32)
    gemm_out_kernel<<<ogrid, 256, GEMM_SMEM_BYTES>>>(pAtt, Wo, bo, out);
}

// round 17
// speedup vs baseline: 1.2399x; 1.2399x over previous
#include <cuda_runtime.h>
#include <math_constants.h>
#include <math.h>
#include <stdint.h>

#define D_MODEL   768
#define NUM_HEADS 12
#define HEAD_DIM  64
#define BATCH     4
#define SEQ       1024
#define NTOK      (BATCH*SEQ)
#define LOG2E     1.4426950408889634f

// ---------------- scratch ----------------------------------------------------
__device__ float g_Q[NTOK * D_MODEL];     // [b,h,s,d]
__device__ float g_K[NTOK * D_MODEL];     // [b,h,s,d]
__device__ float g_V[NTOK * D_MODEL];     // [b,h,s,d]
__device__ float g_att[NTOK * D_MODEL];   // [b,s, h*64+d] flat [4096,768]
__device__ float g_cx[NTOK];
__device__ float g_cy[NTOK];

// ---------------- box centers ----------------------------------------------
__global__ void centers_kernel(const float* __restrict__ boxes) {
    int i = blockIdx.x * blockDim.x + threadIdx.x;
    if (i < NTOK) {
        float4 bx = *(const float4*)(boxes + (size_t)i * 4);
        g_cx[i] = (bx.x + bx.z) * 0.5f;
        g_cy[i] = (bx.y + bx.w) * 0.5f;
    }
}

// ---------------- tf32 / fast-math helpers ----------------------------------
__device__ __forceinline__ uint32_t to_tf32(float x) {
    uint32_t r;
    asm("cvt.rna.tf32.f32 %0, %1;" : "=r"(r) : "f"(x));
    return r;
}

__device__ __forceinline__ void mma_tf32(float* c, uint32_t a0, uint32_t a1,
                                         uint32_t a2, uint32_t a3,
                                         uint32_t b0, uint32_t b1) {
    asm volatile(
        "mma.sync.aligned.m16n8k8.row.col.f32.tf32.tf32.f32 "
        "{%0,%1,%2,%3}, {%4,%5,%6,%7}, {%8,%9}, {%0,%1,%2,%3};\n"
        : "+f"(c[0]), "+f"(c[1]), "+f"(c[2]), "+f"(c[3])
        : "r"(a0), "r"(a1), "r"(a2), "r"(a3), "r"(b0), "r"(b1));
}

__device__ __forceinline__ float rsqrt_approx(float x) {
    float r;
    asm("rsqrt.approx.f32 %0, %1;" : "=f"(r) : "f"(x));
    return r;
}
__device__ __forceinline__ float fast_dist(float dx, float dy) {
    float s = dx * dx + dy * dy;
    return s * rsqrt_approx(fmaxf(s, 1e-30f));
}
__device__ __forceinline__ float ex2_approx(float x) {
    float r;
    asm("ex2.approx.f32 %0, %1;" : "=f"(r) : "f"(x));
    return r;
}

// ---------------- TF32 tensor-core GEMM body (R8/R14 config, PINNED) --------
// BM=BN=128, BK=16, paired-k smem (stride 24), double buffered, one barrier
// per iteration, warps 2(m) x 4(n) warp tile 64x32, 2 CTAs/SM.
#define GSTRIDE 24
#define GEMM_SMEM_BYTES (2 * 2 * 128 * GSTRIDE * 4)   // 49152 B

template<int LAYOUT>
__device__ __forceinline__ void gemm_body(
    const float* __restrict__ A, const float* __restrict__ W,
    const float* __restrict__ bias, float* __restrict__ out)
{
    extern __shared__ uint32_t gsm[];
    uint32_t* As = gsm;                     // [2][128][24]
    uint32_t* Ws = gsm + 2 * 128 * GSTRIDE;

    const int t    = threadIdx.x;
    const int lane = t & 31;
    const int warp = t >> 5;
    const int wm   = warp & 1;
    const int wn   = warp >> 1;
    const int row0 = blockIdx.y * 128;
    const int col0 = blockIdx.x * 128;

    const int sm_m  = t >> 1;
    const int sm_k0 = (t & 1) * 8;
    const float* Ap = A + (size_t)(row0 + sm_m) * D_MODEL + sm_k0;
    const float* Wp = W + (size_t)(col0 + sm_m) * D_MODEL + sm_k0;

    float acc[4][4][4];
#pragma unroll
    for (int mt = 0; mt < 4; mt++)
#pragma unroll
        for (int nt = 0; nt < 4; nt++)
#pragma unroll
            for (int r = 0; r < 4; r++) acc[mt][nt][r] = 0.f;

    float4 a0v, a1v, w0v, w1v;
    a0v = *(const float4*)(Ap);     a1v = *(const float4*)(Ap + 4);
    w0v = *(const float4*)(Wp);     w1v = *(const float4*)(Wp + 4);
    {
        uint32_t* ar = &As[sm_m * GSTRIDE + sm_k0];
        uint32_t* wr = &Ws[sm_m * GSTRIDE + sm_k0];
        *(uint2*)(ar + 0) = make_uint2(to_tf32(a0v.x), to_tf32(a1v.x));
        *(uint2*)(ar + 2) = make_uint2(to_tf32(a0v.y), to_tf32(a1v.y));
        *(uint2*)(ar + 4) = make_uint2(to_tf32(a0v.z), to_tf32(a1v.z));
        *(uint2*)(ar + 6) = make_uint2(to_tf32(a0v.w), to_tf32(a1v.w));
        *(uint2*)(wr + 0) = make_uint2(to_tf32(w0v.x), to_tf32(w1v.x));
        *(uint2*)(wr + 2) = make_uint2(to_tf32(w0v.y), to_tf32(w1v.y));
        *(uint2*)(wr + 4) = make_uint2(to_tf32(w0v.z), to_tf32(w1v.z));
        *(uint2*)(wr + 6) = make_uint2(to_tf32(w0v.w), to_tf32(w1v.w));
    }
    __syncthreads();

    const int NIT = D_MODEL / 16;  // 48
    for (int it = 0; it < NIT; it++) {
        const int cur  = it & 1;
        const bool more = (it + 1) < NIT;
        if (more) {
            const int ko = (it + 1) * 16;
            a0v = *(const float4*)(Ap + ko);  a1v = *(const float4*)(Ap + ko + 4);
            w0v = *(const float4*)(Wp + ko);  w1v = *(const float4*)(Wp + ko + 4);
        }

        const uint32_t* Ab = &As[cur * 128 * GSTRIDE];
        const uint32_t* Wb = &Ws[cur * 128 * GSTRIDE];
#pragma unroll
        for (int ks = 0; ks < 2; ks++) {
            const int base = ks * 8 + 2 * (lane & 3);
            uint2 bf[4];
#pragma unroll
            for (int nt = 0; nt < 4; nt++) {
                int n = wn * 32 + nt * 8 + (lane >> 2);
                bf[nt] = *(const uint2*)&Wb[n * GSTRIDE + base];
            }
#pragma unroll
            for (int mt = 0; mt < 4; mt++) {
                int mr = wm * 64 + mt * 16 + (lane >> 2);
                uint2 lo = *(const uint2*)&Ab[mr * GSTRIDE + base];
                uint2 hi = *(const uint2*)&Ab[(mr + 8) * GSTRIDE + base];
#pragma unroll
                for (int nt = 0; nt < 4; nt++)
                    mma_tf32(acc[mt][nt], lo.x, hi.x, lo.y, hi.y, bf[nt].x, bf[nt].y);
            }
        }

        if (more) {
            const int nxt = cur ^ 1;
            uint32_t* ar = &As[(nxt * 128 + sm_m) * GSTRIDE + sm_k0];
            uint32_t* wr = &Ws[(nxt * 128 + sm_m) * GSTRIDE + sm_k0];
            *(uint2*)(ar + 0) = make_uint2(to_tf32(a0v.x), to_tf32(a1v.x));
            *(uint2*)(ar + 2) = make_uint2(to_tf32(a0v.y), to_tf32(a1v.y));
            *(uint2*)(ar + 4) = make_uint2(to_tf32(a0v.z), to_tf32(a1v.z));
            *(uint2*)(ar + 6) = make_uint2(to_tf32(a0v.w), to_tf32(a1v.w));
            *(uint2*)(wr + 0) = make_uint2(to_tf32(w0v.x), to_tf32(w1v.x));
            *(uint2*)(wr + 2) = make_uint2(to_tf32(w0v.y), to_tf32(w1v.y));
            *(uint2*)(wr + 4) = make_uint2(to_tf32(w0v.z), to_tf32(w1v.z));
            *(uint2*)(wr + 6) = make_uint2(to_tf32(w0v.w), to_tf32(w1v.w));
        }
        __syncthreads();
    }

#pragma unroll
    for (int mt = 0; mt < 4; mt++) {
#pragma unroll
        for (int nt = 0; nt < 4; nt++) {
            int r = row0 + wm * 64 + mt * 16 + (lane >> 2);
            int c = col0 + wn * 32 + nt * 8 + (lane & 3) * 2;
            float b0 = bias[c], b1 = bias[c + 1];
#pragma unroll
            for (int half = 0; half < 2; half++) {
                int rr = r + half * 8;
                float v0 = acc[mt][nt][half * 2 + 0] + b0;
                float v1 = acc[mt][nt][half * 2 + 1] + b1;
                size_t base;
                if (LAYOUT == 1) {
                    int b = rr >> 10, s = rr & 1023;
                    int h = c >> 6, d0 = c & 63;
                    base = (((size_t)(b * NUM_HEADS + h)) * SEQ + s) * HEAD_DIM + d0;
                } else {
                    base = (size_t)rr * D_MODEL + c;
                }
                *(float2*)(out + base) = make_float2(v0, v1);
            }
        }
    }
}

__global__ __launch_bounds__(256, 2) void gemm_qkv_kernel(
    const float* __restrict__ x,
    const float* __restrict__ Wq, const float* __restrict__ Wk,
    const float* __restrict__ Wv,
    const float* __restrict__ bq, const float* __restrict__ bk,
    const float* __restrict__ bv,
    float* __restrict__ oq, float* __restrict__ ok, float* __restrict__ ov)
{
    const int z = blockIdx.z;
    const float* W = (z == 0) ? Wq : (z == 1) ? Wk : Wv;
    const float* b = (z == 0) ? bq : (z == 1) ? bk : bv;
    float*       o = (z == 0) ? oq : (z == 1) ? ok : ov;
    gemm_body<1>(x, W, b, o);
}

__global__ __launch_bounds__(256, 2) void gemm_out_kernel(
    const float* __restrict__ A, const float* __restrict__ W,
    const float* __restrict__ bias, float* __restrict__ out)
{
    gemm_body<0>(A, W, bias, out);
}

// ---------------- attention: R14 structure, Q pre-scaled by 0.125*log2e -----
// 16 chunks of 64 K-rows, SINGLE chunk buffer (75.3 KB -> 3 CTAs/SM, single
// wave). dist via MUFU.RSQ; exp2 via MUFU.EX2. Score scale folded into Q at
// staging (exact relative-error-preserving pre-scale) -> 32 fewer FMUL per
// thread per chunk in the serial softmax section.
#define AQ_STR 72
#define KCH_W  (64 * 72)                 // 4608 words
#define OFF_Q   0
#define OFF_KT  (128 * AQ_STR)           // 9216
#define OFF_VT  (OFF_KT + KCH_W)         // 13824
#define OFF_QCX (OFF_VT + KCH_W)         // 18432
#define OFF_QCY (OFF_QCX + 128)          // 18560
#define OFF_KC  (OFF_QCY + 128)          // 18688: [128] = {cx[64], cy[64]}
#define ATTN_SMEM_BYTES ((OFF_KC + 128) * 4)   // 75264 B

// stage Q tile, multiplying by `scale` before tf32 conversion
__device__ __forceinline__ void stage_paired_q(uint32_t* dst, const float* src,
                                               int t, float scale) {
    const int tr = t >> 1;
    const int half = t & 1;
    const float* p = src + (size_t)tr * HEAD_DIM + half * 32;
    float4 f[8];
#pragma unroll
    for (int u = 0; u < 8; u++) {
        f[u] = *(const float4*)(p + 4 * u);
        f[u].x *= scale; f[u].y *= scale; f[u].z *= scale; f[u].w *= scale;
    }
    uint32_t* row = dst + tr * AQ_STR + half * 32;
#pragma unroll
    for (int gg = 0; gg < 4; gg++) {
        float4 lo = f[2 * gg], hi = f[2 * gg + 1];
        *(uint2*)(row + gg * 8 + 0) = make_uint2(to_tf32(lo.x), to_tf32(hi.x));
        *(uint2*)(row + gg * 8 + 2) = make_uint2(to_tf32(lo.y), to_tf32(hi.y));
        *(uint2*)(row + gg * 8 + 4) = make_uint2(to_tf32(lo.z), to_tf32(hi.z));
        *(uint2*)(row + gg * 8 + 6) = make_uint2(to_tf32(lo.w), to_tf32(hi.w));
    }
}

__device__ __forceinline__ void stage_chunk(uint32_t* smu, size_t headbase,
                                            int bS, int ci, int t) {
    const int kr = t >> 2;
    const int cq = (t & 3) * 16;
    const int g0 = cq >> 3;
    const size_t rbase = headbase + (size_t)(ci * 64 + kr) * HEAD_DIM + cq;
    const float* kp = g_K + rbase;
    const float* vp = g_V + rbase;
    float4 fK[4], fV[4];
#pragma unroll
    for (int u = 0; u < 4; u++) {
        fK[u] = *(const float4*)(kp + 4 * u);
        fV[u] = *(const float4*)(vp + 4 * u);
    }
    float cpref = 0.f;
    if (t < 64)       cpref = g_cx[bS + ci * 64 + t];
    else if (t < 128) cpref = g_cy[bS + ci * 64 + (t - 64)];

    const float* fk = (const float*)fK;
    uint32_t* krow = smu + OFF_KT + kr * 72;
#pragma unroll
    for (int gg = 0; gg < 2; gg++) {
        const float* f = fk + gg * 8;
        *(uint4*)(krow + (g0 + gg) * 8 + 0) =
            make_uint4(to_tf32(f[0]), to_tf32(f[4]), to_tf32(f[1]), to_tf32(f[5]));
        *(uint4*)(krow + (g0 + gg) * 8 + 4) =
            make_uint4(to_tf32(f[2]), to_tf32(f[6]), to_tf32(f[3]), to_tf32(f[7]));
    }
    uint32_t* vrow = smu + OFF_VT + kr * 72 + cq;
#pragma unroll
    for (int u = 0; u < 4; u++)
        *(uint4*)(vrow + 4 * u) = make_uint4(to_tf32(fV[u].x), to_tf32(fV[u].y),
                                             to_tf32(fV[u].z), to_tf32(fV[u].w));
    if (t < 128) ((float*)(smu + OFF_KC))[t] = cpref;
}

__global__ __launch_bounds__(256, 3) void attn_kernel(const float* __restrict__ sbias)
{
    extern __shared__ uint32_t smu[];
    uint32_t* Qs = smu + OFF_Q;
    float* qcx = (float*)(smu + OFF_QCX);
    float* qcy = (float*)(smu + OFF_QCY);

    const int t    = threadIdx.x;
    const int lane = t & 31;
    const int warp = t >> 5;
    const int q    = lane & 3;
    const int bh = blockIdx.y;
    const int b  = bh / NUM_HEADS, h = bh % NUM_HEADS;
    const int q0 = blockIdx.x * 128;
    const float sb2 = sbias[h] * LOG2E;
    const float sc2 = 0.125f * LOG2E;
    const size_t headbase = (size_t)bh * SEQ * HEAD_DIM;
    const int bS = b * SEQ;

    const int r0 = warp * 16 + (lane >> 2);
    const int r1 = r0 + 8;

    stage_paired_q(Qs, g_Q + headbase + (size_t)q0 * HEAD_DIM, t, sc2);
    if (t < 128) {
        qcx[t] = g_cx[bS + q0 + t];
        qcy[t] = g_cy[bS + q0 + t];
    }
    stage_chunk(smu, headbase, bS, 0, t);
    __syncthreads();

    const float qx0 = qcx[r0], qy0 = qcy[r0];
    const float qx1 = qcx[r1], qy1 = qcy[r1];

    float m0 = -CUDART_INF_F, m1 = -CUDART_INF_F, l0 = 0.f, l1 = 0.f;
    float oacc[8][4];
#pragma unroll
    for (int nt = 0; nt < 8; nt++)
#pragma unroll
        for (int r = 0; r < 4; r++) oacc[nt][r] = 0.f;

    const int sA = (lane & ~3) | (q >> 1);
    const int sB = sA + 2;
    const bool qodd = (q & 1) != 0;

    const uint32_t* Kb = smu + OFF_KT;
    const uint32_t* Vb = smu + OFF_VT;
    const float* kcb = (const float*)(smu + OFF_KC);

    const int NCHUNK = SEQ / 64;  // 16
    for (int ci = 0; ci < NCHUNK; ci++) {
        // ---- S = (Q*sc2) K^T : scores arrive pre-scaled ----
        float sacc[8][4];
#pragma unroll
        for (int nt = 0; nt < 8; nt++)
            sacc[nt][0] = sacc[nt][1] = sacc[nt][2] = sacc[nt][3] = 0.f;
#pragma unroll
        for (int ks = 0; ks < 8; ks++) {
            uint2 qlo = *(const uint2*)&Qs[r0 * AQ_STR + ks * 8 + 2 * q];
            uint2 qhi = *(const uint2*)&Qs[r1 * AQ_STR + ks * 8 + 2 * q];
#pragma unroll
            for (int nt = 0; nt < 8; nt++) {
                int col = nt * 8 + (lane >> 2);
                uint2 bv = *(const uint2*)&Kb[col * 72 + ks * 8 + 2 * q];
                mma_tf32(sacc[nt], qlo.x, qhi.x, qlo.y, qhi.y, bv.x, bv.y);
            }
        }

        // ---- bias (fast dist), row maxima ----
        float pm0 = -CUDART_INF_F, pm1 = -CUDART_INF_F;
#pragma unroll
        for (int nt = 0; nt < 8; nt++) {
            const int c0 = nt * 8 + 2 * q;
            const float kx0 = kcb[c0], kx1 = kcb[c0 + 1];
            const float ky0 = kcb[64 + c0], ky1 = kcb[64 + c0 + 1];
            sacc[nt][0] -= fast_dist(qx0 - kx0, qy0 - ky0) * sb2;
            sacc[nt][1] -= fast_dist(qx0 - kx1, qy0 - ky1) * sb2;
            sacc[nt][2] -= fast_dist(qx1 - kx0, qy1 - ky0) * sb2;
            sacc[nt][3] -= fast_dist(qx1 - kx1, qy1 - ky1) * sb2;
            pm0 = fmaxf(pm0, fmaxf(sacc[nt][0], sacc[nt][1]));
            pm1 = fmaxf(pm1, fmaxf(sacc[nt][2], sacc[nt][3]));
        }
        pm0 = fmaxf(pm0, __shfl_xor_sync(0xffffffffu, pm0, 1));
        pm0 = fmaxf(pm0, __shfl_xor_sync(0xffffffffu, pm0, 2));
        pm1 = fmaxf(pm1, __shfl_xor_sync(0xffffffffu, pm1, 1));
        pm1 = fmaxf(pm1, __shfl_xor_sync(0xffffffffu, pm1, 2));

        const float mn0 = fmaxf(m0, pm0), mn1 = fmaxf(m1, pm1);
        const float sc0 = ex2_approx(m0 - mn0), sc1 = ex2_approx(m1 - mn1);
        m0 = mn0; m1 = mn1;
#pragma unroll
        for (int nt = 0; nt < 8; nt++) {
            oacc[nt][0] *= sc0; oacc[nt][1] *= sc0;
            oacc[nt][2] *= sc1; oacc[nt][3] *= sc1;
        }

        // ---- p = exp2 (in place), row sums ----
        float s0 = 0.f, s1 = 0.f;
#pragma unroll
        for (int nt = 0; nt < 8; nt++) {
            sacc[nt][0] = ex2_approx(sacc[nt][0] - mn0);
            sacc[nt][1] = ex2_approx(sacc[nt][1] - mn0);
            sacc[nt][2] = ex2_approx(sacc[nt][2] - mn1);
            sacc[nt][3] = ex2_approx(sacc[nt][3] - mn1);
            s0 += sacc[nt][0] + sacc[nt][1];
            s1 += sacc[nt][2] + sacc[nt][3];
        }
        s0 += __shfl_xor_sync(0xffffffffu, s0, 1);
        s0 += __shfl_xor_sync(0xffffffffu, s0, 2);
        s1 += __shfl_xor_sync(0xffffffffu, s1, 1);
        s1 += __shfl_xor_sync(0xffffffffu, s1, 2);
        l0 = l0 * sc0 + s0;
        l1 = l1 * sc1 + s1;

        // ---- O += P V : shuffle-transpose c-frag -> a-frag, then mma ----
#pragma unroll
        for (int ks = 0; ks < 8; ks++) {
            float u0 = __shfl_sync(0xffffffffu, sacc[ks][0], sA);
            float u1 = __shfl_sync(0xffffffffu, sacc[ks][1], sA);
            float v0 = __shfl_sync(0xffffffffu, sacc[ks][0], sB);
            float v1 = __shfl_sync(0xffffffffu, sacc[ks][1], sB);
            float w0 = __shfl_sync(0xffffffffu, sacc[ks][2], sA);
            float w1 = __shfl_sync(0xffffffffu, sacc[ks][3], sA);
            float x0 = __shfl_sync(0xffffffffu, sacc[ks][2], sB);
            float x1 = __shfl_sync(0xffffffffu, sacc[ks][3], sB);
            uint32_t pa0 = to_tf32(qodd ? u1 : u0);
            uint32_t pa2 = to_tf32(qodd ? v1 : v0);
            uint32_t pa1 = to_tf32(qodd ? w1 : w0);
            uint32_t pa3 = to_tf32(qodd ? x1 : x0);

            const int krow = ks * 8 + q;
            const uint32_t* vr0 = &Vb[krow * 72 + (lane >> 2)];
            const uint32_t* vr1 = &Vb[(krow + 4) * 72 + (lane >> 2)];
#pragma unroll
            for (int nt = 0; nt < 8; nt++) {
                uint32_t vb0 = vr0[nt * 8];
                uint32_t vb1 = vr1[nt * 8];
                mma_tf32(oacc[nt], pa0, pa1, pa2, pa3, vb0, vb1);
            }
        }

        if (ci + 1 < NCHUNK) {
            __syncthreads();
            stage_chunk(smu, headbase, bS, ci + 1, t);
            __syncthreads();
        }
    }

    const float inv0 = 1.f / l0, inv1 = 1.f / l1;
#pragma unroll
    for (int nt = 0; nt < 8; nt++) {
        const int d0 = nt * 8 + 2 * q;
        size_t base0 = ((size_t)(bS + q0 + r0)) * D_MODEL + h * HEAD_DIM + d0;
        size_t base1 = ((size_t)(bS + q0 + r1)) * D_MODEL + h * HEAD_DIM + d0;
        *(float2*)(g_att + base0) = make_float2(oacc[nt][0] * inv0, oacc[nt][1] * inv0);
        *(float2*)(g_att + base1) = make_float2(oacc[nt][2] * inv1, oacc[nt][3] * inv1);
    }
}

// ---------------- launch ----------------------------------------------------
extern "C" void kernel_launch(void* const* d_in, const int* in_sizes, int n_in,
                              void* d_out, int out_size)
{
    const float* x     = (const float*)d_in[0];
    const float* boxes = (const float*)d_in[1];
    const float* Wq    = (const float*)d_in[2];
    const float* bq    = (const float*)d_in[3];
    const float* Wk    = (const float*)d_in[4];
    const float* bk    = (const float*)d_in[5];
    const float* Wv    = (const float*)d_in[6];
    const float* bv    = (const float*)d_in[7];
    const float* Wo    = (const float*)d_in[8];
    const float* bo    = (const float*)d_in[9];
    const float* sbias = (const float*)d_in[10];
    float* out = (float*)d_out;

    float *pQ, *pK, *pV, *pAtt;
    cudaGetSymbolAddress((void**)&pQ,   g_Q);
    cudaGetSymbolAddress((void**)&pK,   g_K);
    cudaGetSymbolAddress((void**)&pV,   g_V);
    cudaGetSymbolAddress((void**)&pAtt, g_att);

    cudaFuncSetAttribute(gemm_qkv_kernel,
        cudaFuncAttributeMaxDynamicSharedMemorySize, GEMM_SMEM_BYTES);
    cudaFuncSetAttribute(gemm_out_kernel,
        cudaFuncAttributeMaxDynamicSharedMemorySize, GEMM_SMEM_BYTES);
    cudaFuncSetAttribute(attn_kernel,
        cudaFuncAttributeMaxDynamicSharedMemorySize, ATTN_SMEM_BYTES);

    centers_kernel<<<(NTOK + 255) / 256, 256>>>(boxes);

    dim3 qkvgrid(D_MODEL / 128, NTOK / 128, 3);   // (6, 32, 3)
    gemm_qkv_kernel<<<qkvgrid, 256, GEMM_SMEM_BYTES>>>(
        x, Wq, Wk, Wv, bq, bk, bv, pQ, pK, pV);

    dim3 agrid(SEQ / 128, BATCH * NUM_HEADS);     // (8, 48)
    attn_kernel<<<agrid, 256, ATTN_SMEM_BYTES>>>(sbias);

    dim3 ogrid(D_MODEL / 128, NTOK / 128);        // (6, 32)
    gemm_out_kernel<<<ogrid, 256, GEMM_SMEM_BYTES>>>(pAtt, Wo, bo, out);
}